// round 13
// baseline (speedup 1.0000x reference)
#include <cuda_runtime.h>
#include <cuda_fp16.h>
#include <cstdint>

#define BN   1024
#define TT   256
#define EMB  10
#define HID  256
#define CLS  10

#define NCTA  128
#define NTHR  512
#define MTILE 32       // batch rows per CTA
#define NGATE 256      // gate cols per CTA (gate-pair-major: (g,i)[0,128) | (f,o)[128,256))
#define GRPSZ 4        // CTAs per cluster (column blocks of one batch group)

#define KTOT  272      // 256 recurrent + 16 ext (10 emb + bias-1 + pad)
#define KC    17
#define RS    544      // SMEM row stride bytes (272 fp16)

// ---------------- persistent device state ---------------------------------
__device__ __half    d_Ef[TT * BN * 16];    // [t][b][16] fp16 emb (incl bias col)
__device__ float     d_Hf[BN * HID];        // final h fp32 for projection

// ---------------- helpers --------------------------------------------------
__device__ __forceinline__ uint32_t smem_u32(const void* p) {
    uint32_t a;
    asm("{ .reg .u64 t; cvta.to.shared.u64 t, %1; cvt.u32.u64 %0, t; }" : "=r"(a) : "l"(p));
    return a;
}
__device__ __forceinline__ float ftanha(float x) {
    float y; asm("tanh.approx.f32 %0, %1;" : "=f"(y) : "f"(x)); return y;
}
// two sigmoids in one MUFU via tanh.approx.f16x2
__device__ __forceinline__ __half2 sig2(float a, float b) {
    __half2 x = __floats2half2_rn(0.5f * a, 0.5f * b);
    uint32_t xi = *(uint32_t*)&x, ti;
    asm("tanh.approx.f16x2 %0, %1;" : "=r"(ti) : "r"(xi));
    __half2 t = *(__half2*)&ti;
    const __half2 hh = __float2half2_rn(0.5f);
    return __hfma2(t, hh, hh);
}
__device__ __forceinline__ void ldsm_x4(uint32_t* r, uint32_t addr) {
    asm volatile("ldmatrix.sync.aligned.m8n8.x4.shared.b16 {%0,%1,%2,%3}, [%4];"
                 : "=r"(r[0]), "=r"(r[1]), "=r"(r[2]), "=r"(r[3]) : "r"(addr));
}
__device__ __forceinline__ void mma16816(float* d, const uint32_t* a, const uint32_t* b) {
    asm volatile("mma.sync.aligned.m16n8k16.row.col.f32.f16.f16.f32 "
                 "{%0,%1,%2,%3}, {%4,%5,%6,%7}, {%8,%9}, {%0,%1,%2,%3};"
                 : "+f"(d[0]), "+f"(d[1]), "+f"(d[2]), "+f"(d[3])
                 : "r"(a[0]), "r"(a[1]), "r"(a[2]), "r"(a[3]), "r"(b[0]), "r"(b[1]));
}
__device__ __forceinline__ uint32_t mapa_u32(uint32_t addr, uint32_t rank) {
    uint32_t r;
    asm("mapa.shared::cluster.u32 %0, %1, %2;" : "=r"(r) : "r"(addr), "r"(rank));
    return r;
}
__device__ __forceinline__ void st_cluster_u4(uint32_t addr, uint4 v) {
    asm volatile("st.shared::cluster.v4.u32 [%0], {%1,%2,%3,%4};"
                 :: "r"(addr), "r"(v.x), "r"(v.y), "r"(v.z), "r"(v.w) : "memory");
}
#define CLUSTER_ARRIVE() asm volatile("barrier.cluster.arrive.aligned;" ::: "memory")
#define CLUSTER_WAIT()   asm volatile("barrier.cluster.wait.aligned;"   ::: "memory")
#define CLUSTER_SYNC() do { CLUSTER_ARRIVE(); CLUSTER_WAIT(); } while (0)

// SMEM byte offsets from aligned base
#define SO_W   0                         // [256 n][RS]  139264
#define ASZ    17408                     // one A buffer [32 m][RS]
#define SO_A   139264                    // A[2] double-buffered (34816)
#define SO_HB  174080                    // h bounce [32][64] fp16 = 4096
#define SMEM_REQ (178176 + 2048)

// ---------------- prologue: embeddings (fp16, bias col) --------------------
__global__ void embed_kernel(const int* __restrict__ x, const float* __restrict__ emb) {
    int i = blockIdx.x * blockDim.x + threadIdx.x;   // 0 .. BN*TT-1
    int b = i & (BN - 1);
    int t = i >> 10;
    int tok = x[b * TT + t];
    __half e16[16];
#pragma unroll
    for (int e = 0; e < 16; e++) {
        float v = (e < EMB) ? __ldg(&emb[tok * EMB + e]) : (e == EMB ? 1.0f : 0.0f);
        e16[e] = __float2half(v);
    }
    size_t off = (size_t)(t * BN + b) * 16;
    ((uint4*)(d_Ef + off))[0] = ((uint4*)e16)[0];
    ((uint4*)(d_Ef + off))[1] = ((uint4*)e16)[1];
}

// ---------------- main persistent LSTM kernel ------------------------------
__global__ void __launch_bounds__(NTHR, 1) __cluster_dims__(GRPSZ, 1, 1)
lstm_kernel(
    const float* __restrict__ Wgh, const float* __restrict__ Wih,
    const float* __restrict__ Wfh, const float* __restrict__ Woh,
    const float* __restrict__ Wgx, const float* __restrict__ Wix,
    const float* __restrict__ Wfx, const float* __restrict__ Wox,
    const float* __restrict__ bg,  const float* __restrict__ bi,
    const float* __restrict__ bf,  const float* __restrict__ bo)
{
    extern __shared__ char smem_raw[];
    char* base = (char*)(((uintptr_t)smem_raw + 1023) & ~(uintptr_t)1023);
    const uint32_t sb = smem_u32(base);

    const int tid = threadIdx.x;
    const int l   = tid & 31;
    const int w   = tid >> 5;
    const int mh  = w & 1;               // warp's M half (16 rows)
    const int nq  = w >> 1;              // warp's unit-octet (8 units)
    const int cb  = blockIdx.x & 3;      // cluster rank == column block
    const int grp = blockIdx.x >> 2;     // batch group
    const int ug0 = cb * 64;
    const int b0  = grp * MTILE;

    // peer SMEM bases (incl. self)
    uint32_t peer[GRPSZ];
#pragma unroll
    for (int r = 0; r < GRPSZ; r++) peer[r] = mapa_u32(sb, (uint32_t)r);

    // ---- one-time: stage W fp16, gate-pair-major N layout ------------------
    {
        const float* Whp[4] = {Wgh, Wih, Wfh, Woh};
        const float* Wxp[4] = {Wgx, Wix, Wfx, Wox};
        const float* bp4[4] = {bg, bi, bf, bo};
        for (int idx = tid; idx < NGATE * KTOT; idx += NTHR) {
            int n = idx & 255, k = idx >> 8;
            int g = ((n >> 7) << 1) | (n & 1);
            int u = ug0 + ((n & 127) >> 1);
            float v;
            if (k < 256)       v = Whp[g][k * HID + u];
            else if (k < 266)  v = Wxp[g][(k - 256) * HID + u];
            else if (k == 266) v = bp4[g][u];
            else               v = 0.0f;
            int off = n * RS + k * 2;
            int sw  = off ^ ((n & 7) << 4);
            *(__half*)(base + SO_W + sw) = __float2half(v);
        }
    }

    // ---- prologue: A[0] = h0 (zeros) + emb(0) ext --------------------------
    {
        uint4 z = make_uint4(0, 0, 0, 0);
        for (int g2 = tid; g2 < ASZ / 16; g2 += NTHR)
            *(uint4*)(base + SO_A + g2 * 16) = z;
        __syncthreads();
        if (tid < 64) {
            int row = tid >> 1, g2 = tid & 1;
            int off = row * RS + (32 + g2) * 16;
            int sw  = off ^ ((row & 7) << 4);
            *(uint4*)(base + SO_A + sw) =
                __ldg((const uint4*)(d_Ef + (size_t)(b0 + row) * 16) + g2);
        }
    }
    __syncthreads();
    CLUSTER_SYNC();

    // ---- fragment addresses ------------------------------------------------
    const int arow = mh * 16 + (l & 15);
    const uint32_t aBase = sb + SO_A + arow * RS + ((l >> 4) << 4);
    const uint32_t aXor  = (arow & 7) << 4;
    uint32_t wBase[2];                    // [0]=(g,i) cols, [1]=(f,o) cols
#pragma unroll
    for (int gp = 0; gp < 2; gp++) {
        int n = gp * 128 + nq * 16 + ((l >> 4) << 3) + (l & 7);
        wBase[gp] = sb + SO_W + n * RS + (((l >> 3) & 1) << 4);
    }
    const uint32_t wXor = (l & 7) << 4;

    float cst[4];
#pragma unroll
    for (int q = 0; q < 4; q++) cst[q] = 0.0f;

#define DO_KC(kcv) do {                                                       \
        const uint32_t kb = (uint32_t)(kcv) * 32;                             \
        uint32_t af[4];                                                       \
        ldsm_x4(af, (aBase + rbo + kb) ^ aXor);                               \
        uint32_t wf0[4], wf1[4];                                              \
        ldsm_x4(wf0, (wBase[0] + kb) ^ wXor);                                 \
        ldsm_x4(wf1, (wBase[1] + kb) ^ wXor);                                 \
        mma16816(acc,      af, &wf0[0]);                                      \
        mma16816(acc + 4,  af, &wf0[2]);                                      \
        mma16816(acc + 8,  af, &wf1[0]);                                      \
        mma16816(acc + 12, af, &wf1[2]);                                      \
    } while (0)

    for (int t = 0; t < TT; t++) {
        const uint32_t rbo = (uint32_t)(t & 1) * ASZ;
        const uint32_t wbo = (uint32_t)((t + 1) & 1) * ASZ;

        float acc[16];
#pragma unroll
        for (int q = 0; q < 16; q++) acc[q] = 0.0f;

        // hoist emb(t+1) LDG into registers (latency hidden under wait+[C])
        const bool doemb = (t < TT - 1) && (tid < 64);
        uint4 ev;
        if (doemb)
            ev = __ldg((const uint4*)(d_Ef + (size_t)((t + 1) * BN + b0 + (tid >> 1)) * 16)
                       + (tid & 1));

        // [A] part1: locally-produced kcs (own column region + ext) ----------
        {
            const int cbk = cb * 4;
#pragma unroll
            for (int i = 0; i < 4; i++) DO_KC(cbk + i);
            DO_KC(16);
        }

        // prefetch W fragments of the first peer kc (static data, no hazard)
        uint32_t wfp0[4], wfp1[4];
        const uint32_t kbp = (uint32_t)(((cb + 1) & 3) << 2) * 32;
        ldsm_x4(wfp0, (wBase[0] + kbp) ^ wXor);
        ldsm_x4(wfp1, (wBase[1] + kbp) ^ wXor);

        // [B] wait for peers' h(t) slices (arrivals from step t-1) -----------
        if (t > 0) CLUSTER_WAIT();

        // [C] part2: peer kcs, nearest-producer order; first kc uses prefetch
        {
            uint32_t af[4];
            ldsm_x4(af, (aBase + rbo + kbp) ^ aXor);
            mma16816(acc,      af, &wfp0[0]);
            mma16816(acc + 4,  af, &wfp0[2]);
            mma16816(acc + 8,  af, &wfp1[0]);
            mma16816(acc + 12, af, &wfp1[2]);
        }
#pragma unroll
        for (int i = 1; i < 4; i++) DO_KC((((cb + 1) & 3) << 2) + i);
#pragma unroll
        for (int rr = 2; rr < 4; rr++) {
            const int r4 = (((cb + rr) & 3) << 2);
#pragma unroll
            for (int i = 0; i < 4; i++) DO_KC(r4 + i);
        }

        // [D] store the prefetched emb(t+1) ext into A[wb] -------------------
        if (doemb) {
            int row = tid >> 1, g2 = tid & 1;
            int off = row * RS + (32 + g2) * 16;
            int sw  = off ^ ((row & 7) << 4);
            *(uint4*)(base + SO_A + wbo + sw) = ev;
        }

        // [D] gates: packed f16x2 sigmoids, fp32 tanh ------------------------
        {
            float zgv[4], ziv[4], zfv[4], zov[4];
#pragma unroll
            for (int q = 0; q < 4; q++) {
                int ai = (q >> 1) * 4 + (q & 1) * 2;
                zgv[q] = acc[ai];     ziv[q] = acc[ai + 1];
                zfv[q] = acc[8 + ai]; zov[q] = acc[8 + ai + 1];
            }
            __half2 si01 = sig2(ziv[0], ziv[1]), si23 = sig2(ziv[2], ziv[3]);
            __half2 sf01 = sig2(zfv[0], zfv[1]), sf23 = sig2(zfv[2], zfv[3]);
            __half2 so01 = sig2(zov[0], zov[1]), so23 = sig2(zov[2], zov[3]);
            float si[4] = {__low2float(si01), __high2float(si01),
                           __low2float(si23), __high2float(si23)};
            float sf[4] = {__low2float(sf01), __high2float(sf01),
                           __low2float(sf23), __high2float(sf23)};
            float so[4] = {__low2float(so01), __high2float(so01),
                           __low2float(so23), __high2float(so23)};
            __half* Hb = (__half*)(base + SO_HB);
#pragma unroll
            for (int q = 0; q < 4; q++) {
                float c = ftanha(zgv[q]) * si[q] + cst[q] * sf[q];
                cst[q] = c;
                float h = ftanha(c) * so[q];
                int row = mh * 16 + (l >> 2) + (q & 1) * 8;       // 0..31
                int u   = nq * 8 + (q >> 1) * 4 + (l & 3);        // 0..63
                if (t < TT - 1) {
                    Hb[row * 64 + u] = __float2half(h);
                } else {
                    d_Hf[(size_t)(b0 + row) * HID + ug0 + u] = h;
                }
            }
        }
        if (t == TT - 1) break;

        // [E] broadcast my h slice -> all 4 peers' A[wb] ---------------------
        __syncthreads();
        if (tid < 256) {
            int row = tid >> 3, chunk = tid & 7;          // 256 granules of 16B
            uint4 v = *(const uint4*)(base + SO_HB + row * 128 + chunk * 16);
            int off = row * RS + cb * 128 + chunk * 16;
            uint32_t dst = (uint32_t)(SO_A) + wbo + (uint32_t)(off ^ ((row & 7) << 4));
#pragma unroll
            for (int r = 0; r < GRPSZ; r++)
                st_cluster_u4(peer[r] + dst, v);
        }

        // [F] signal my slice stored; order own-region stores for next [A] ---
        CLUSTER_ARRIVE();
        __syncthreads();
    }
    CLUSTER_SYNC();   // no CTA exits while peers may still write its SMEM
#undef DO_KC
}

// ---------------- final projection -----------------------------------------
__global__ void proj_kernel(const float* __restrict__ Wph, const float* __restrict__ bpv,
                            float* __restrict__ out) {
    __shared__ float Ws[HID * CLS];
    int tid = threadIdx.x;
    for (int idx = tid; idx < HID * CLS; idx += blockDim.x) Ws[idx] = Wph[idx];
    __syncthreads();
    int b = blockIdx.x * blockDim.x + tid;
    float acc[CLS];
#pragma unroll
    for (int c = 0; c < CLS; c++) acc[c] = bpv[c];
    const float* hrow = d_Hf + (size_t)b * HID;
    for (int k = 0; k < HID; k++) {
        float h = hrow[k];
#pragma unroll
        for (int c = 0; c < CLS; c++) acc[c] += h * Ws[k * CLS + c];
    }
#pragma unroll
    for (int c = 0; c < CLS; c++) out[b * CLS + c] = acc[c];
}

extern "C" void kernel_launch(void* const* d_in, const int* in_sizes, int n_in,
                              void* d_out, int out_size) {
    const int*   x   = (const int*)d_in[0];
    const float* emb = (const float*)d_in[1];
    const float* Wgx = (const float*)d_in[2];
    const float* Wgh = (const float*)d_in[3];
    const float* bg  = (const float*)d_in[4];
    const float* Wix = (const float*)d_in[5];
    const float* Wih = (const float*)d_in[6];
    const float* bi  = (const float*)d_in[7];
    const float* Wfx = (const float*)d_in[8];
    const float* Wfh = (const float*)d_in[9];
    const float* bf  = (const float*)d_in[10];
    const float* Wox = (const float*)d_in[11];
    const float* Woh = (const float*)d_in[12];
    const float* bo  = (const float*)d_in[13];
    const float* Wph = (const float*)d_in[14];
    const float* bp  = (const float*)d_in[15];
    float* out = (float*)d_out;

    embed_kernel<<<(BN * TT) / 256, 256>>>(x, emb);

    cudaFuncSetAttribute(lstm_kernel, cudaFuncAttributeMaxDynamicSharedMemorySize, SMEM_REQ);
    lstm_kernel<<<NCTA, NTHR, SMEM_REQ>>>(Wgh, Wih, Wfh, Woh,
                                          Wgx, Wix, Wfx, Wox,
                                          bg, bi, bf, bo);

    proj_kernel<<<BN / 128, 128>>>(Wph, bp, out);
}

// round 15
// speedup vs baseline: 1.1134x; 1.1134x over previous
#include <cuda_runtime.h>
#include <cuda_fp16.h>
#include <cstdint>

#define BN   1024
#define TT   256
#define EMB  10
#define HID  256
#define CLS  10

#define NCTA  128
#define NTHR  512
#define MTILE 32       // batch rows per CTA
#define NGATE 256      // gate cols per CTA (gate-pair-major: (g,i)[0,128) | (f,o)[128,256))
#define GRPSZ 4        // CTAs per cluster (column blocks of one batch group)

#define KTOT  272      // 256 recurrent + 16 ext (10 emb + bias-1 + pad)
#define KC    17
#define RS    544      // SMEM row stride bytes (272 fp16)

// ---------------- persistent device state ---------------------------------
__device__ __half    d_Ef[TT * BN * 16];    // [t][b][16] fp16 emb (incl bias col)
__device__ float     d_Hf[BN * HID];        // final h fp32 for projection

// ---------------- helpers --------------------------------------------------
__device__ __forceinline__ uint32_t smem_u32(const void* p) {
    uint32_t a;
    asm("{ .reg .u64 t; cvta.to.shared.u64 t, %1; cvt.u32.u64 %0, t; }" : "=r"(a) : "l"(p));
    return a;
}
__device__ __forceinline__ float ftanha(float x) {
    float y; asm("tanh.approx.f32 %0, %1;" : "=f"(y) : "f"(x)); return y;
}
__device__ __forceinline__ float fsigt(float x) {     // sigmoid via tanh.approx
    return fmaf(ftanha(0.5f * x), 0.5f, 0.5f);
}
__device__ __forceinline__ void ldsm_x4(uint32_t* r, uint32_t addr) {
    asm volatile("ldmatrix.sync.aligned.m8n8.x4.shared.b16 {%0,%1,%2,%3}, [%4];"
                 : "=r"(r[0]), "=r"(r[1]), "=r"(r[2]), "=r"(r[3]) : "r"(addr));
}
__device__ __forceinline__ void mma16816(float* d, const uint32_t* a, const uint32_t* b) {
    asm volatile("mma.sync.aligned.m16n8k16.row.col.f32.f16.f16.f32 "
                 "{%0,%1,%2,%3}, {%4,%5,%6,%7}, {%8,%9}, {%0,%1,%2,%3};"
                 : "+f"(d[0]), "+f"(d[1]), "+f"(d[2]), "+f"(d[3])
                 : "r"(a[0]), "r"(a[1]), "r"(a[2]), "r"(a[3]), "r"(b[0]), "r"(b[1]));
}
__device__ __forceinline__ uint32_t mapa_u32(uint32_t addr, uint32_t rank) {
    uint32_t r;
    asm("mapa.shared::cluster.u32 %0, %1, %2;" : "=r"(r) : "r"(addr), "r"(rank));
    return r;
}
__device__ __forceinline__ void st_cluster_u4(uint32_t addr, uint4 v) {
    asm volatile("st.shared::cluster.v4.u32 [%0], {%1,%2,%3,%4};"
                 :: "r"(addr), "r"(v.x), "r"(v.y), "r"(v.z), "r"(v.w) : "memory");
}
__device__ __forceinline__ void mbar_init(uint32_t mbar, uint32_t cnt) {
    asm volatile("mbarrier.init.shared.b64 [%0], %1;" :: "r"(mbar), "r"(cnt) : "memory");
}
// remote arrive with cluster-scope release (publishes my prior DSMEM stores)
__device__ __forceinline__ void mbar_arrive_remote(uint32_t remote_mbar) {
    asm volatile("mbarrier.arrive.release.cluster.shared::cluster.b64 _, [%0];"
                 :: "r"(remote_mbar) : "memory");
}
// parity wait with cluster-scope acquire
__device__ __forceinline__ void mbar_wait_cl(uint32_t mbar, uint32_t parity) {
    asm volatile(
        "{\n\t.reg .pred P;\n\t"
        "WL%=:\n\t"
        "mbarrier.try_wait.parity.acquire.cluster.shared::cta.b64 P, [%0], %1;\n\t"
        "@P bra WD%=;\n\t"
        "bra WL%=;\n\t"
        "WD%=:\n\t}"
        :: "r"(mbar), "r"(parity) : "memory");
}
#define CLUSTER_ARRIVE() asm volatile("barrier.cluster.arrive.aligned;" ::: "memory")
#define CLUSTER_WAIT()   asm volatile("barrier.cluster.wait.aligned;"   ::: "memory")
#define CLUSTER_SYNC() do { CLUSTER_ARRIVE(); CLUSTER_WAIT(); } while (0)

// SMEM byte offsets from aligned base
#define SO_W   0                         // [256 n][RS]  139264
#define ASZ    17408                     // one A buffer [32 m][RS]
#define SO_A   139264                    // A[2] double-buffered (34816)
#define SO_HB  174080                    // h bounce [32][64] fp16 = 4096
#define SO_MB  178176                    // 4 mbarriers (8B each, slot = source rank)
#define SMEM_REQ (178240 + 2048)

// ---------------- prologue: embeddings (fp16, bias col) --------------------
__global__ void embed_kernel(const int* __restrict__ x, const float* __restrict__ emb) {
    int i = blockIdx.x * blockDim.x + threadIdx.x;   // 0 .. BN*TT-1
    int b = i & (BN - 1);
    int t = i >> 10;
    int tok = x[b * TT + t];
    __half e16[16];
#pragma unroll
    for (int e = 0; e < 16; e++) {
        float v = (e < EMB) ? __ldg(&emb[tok * EMB + e]) : (e == EMB ? 1.0f : 0.0f);
        e16[e] = __float2half(v);
    }
    size_t off = (size_t)(t * BN + b) * 16;
    ((uint4*)(d_Ef + off))[0] = ((uint4*)e16)[0];
    ((uint4*)(d_Ef + off))[1] = ((uint4*)e16)[1];
}

// ---------------- main persistent LSTM kernel ------------------------------
__global__ void __launch_bounds__(NTHR, 1) __cluster_dims__(GRPSZ, 1, 1)
lstm_kernel(
    const float* __restrict__ Wgh, const float* __restrict__ Wih,
    const float* __restrict__ Wfh, const float* __restrict__ Woh,
    const float* __restrict__ Wgx, const float* __restrict__ Wix,
    const float* __restrict__ Wfx, const float* __restrict__ Wox,
    const float* __restrict__ bg,  const float* __restrict__ bi,
    const float* __restrict__ bf,  const float* __restrict__ bo)
{
    extern __shared__ char smem_raw[];
    char* base = (char*)(((uintptr_t)smem_raw + 1023) & ~(uintptr_t)1023);
    const uint32_t sb = smem_u32(base);

    const int tid = threadIdx.x;
    const int l   = tid & 31;
    const int w   = tid >> 5;
    const int mh  = w & 1;               // warp's M half (16 rows)
    const int nq  = w >> 1;              // warp's unit-octet (8 units)
    const int cb  = blockIdx.x & 3;      // cluster rank == column block
    const int grp = blockIdx.x >> 2;     // batch group
    const int ug0 = cb * 64;
    const int b0  = grp * MTILE;

    // peer SMEM bases (incl. self)
    uint32_t peer[GRPSZ];
#pragma unroll
    for (int r = 0; r < GRPSZ; r++) peer[r] = mapa_u32(sb, (uint32_t)r);

    // ---- one-time: stage W fp16, gate-pair-major N layout ------------------
    {
        const float* Whp[4] = {Wgh, Wih, Wfh, Woh};
        const float* Wxp[4] = {Wgx, Wix, Wfx, Wox};
        const float* bp4[4] = {bg, bi, bf, bo};
        for (int idx = tid; idx < NGATE * KTOT; idx += NTHR) {
            int n = idx & 255, k = idx >> 8;
            int g = ((n >> 7) << 1) | (n & 1);
            int u = ug0 + ((n & 127) >> 1);
            float v;
            if (k < 256)       v = Whp[g][k * HID + u];
            else if (k < 266)  v = Wxp[g][(k - 256) * HID + u];
            else if (k == 266) v = bp4[g][u];
            else               v = 0.0f;
            int off = n * RS + k * 2;
            int sw  = off ^ ((n & 7) << 4);
            *(__half*)(base + SO_W + sw) = __float2half(v);
        }
    }

    // ---- prologue: A[0] = h0 (zeros) + emb(0) ext; init mbarriers ----------
    if (tid == 0) {
#pragma unroll
        for (int r = 0; r < GRPSZ; r++) mbar_init(sb + SO_MB + r * 8, 1);
    }
    {
        uint4 z = make_uint4(0, 0, 0, 0);
        for (int g2 = tid; g2 < ASZ / 16; g2 += NTHR)
            *(uint4*)(base + SO_A + g2 * 16) = z;
        __syncthreads();
        if (tid < 64) {
            int row = tid >> 1, g2 = tid & 1;
            int off = row * RS + (32 + g2) * 16;
            int sw  = off ^ ((row & 7) << 4);
            *(uint4*)(base + SO_A + sw) =
                __ldg((const uint4*)(d_Ef + (size_t)(b0 + row) * 16) + g2);
        }
    }
    __syncthreads();
    CLUSTER_SYNC();    // mbarrier inits + A[0] visible cluster-wide

    // ---- fragment addresses ------------------------------------------------
    const int arow = mh * 16 + (l & 15);
    const uint32_t aBase = sb + SO_A + arow * RS + ((l >> 4) << 4);
    const uint32_t aXor  = (arow & 7) << 4;
    uint32_t wBase[2];                    // [0]=(g,i) cols, [1]=(f,o) cols
#pragma unroll
    for (int gp = 0; gp < 2; gp++) {
        int n = gp * 128 + nq * 16 + ((l >> 4) << 3) + (l & 7);
        wBase[gp] = sb + SO_W + n * RS + (((l >> 3) & 1) << 4);
    }
    const uint32_t wXor = (l & 7) << 4;

    // permanent register cache: W fragments of the first peer kc (static)
    const uint32_t kbp = (uint32_t)(((cb + 1) & 3) << 2) * 32;
    uint32_t wfp0[4], wfp1[4];
    ldsm_x4(wfp0, (wBase[0] + kbp) ^ wXor);
    ldsm_x4(wfp1, (wBase[1] + kbp) ^ wXor);

    float cst[4];
#pragma unroll
    for (int q = 0; q < 4; q++) cst[q] = 0.0f;

#define DO_KC(kcv) do {                                                       \
        const uint32_t kb = (uint32_t)(kcv) * 32;                             \
        uint32_t af[4];                                                       \
        ldsm_x4(af, (aBase + rbo + kb) ^ aXor);                               \
        uint32_t wf0[4], wf1[4];                                              \
        ldsm_x4(wf0, (wBase[0] + kb) ^ wXor);                                 \
        ldsm_x4(wf1, (wBase[1] + kb) ^ wXor);                                 \
        mma16816(acc,      af, &wf0[0]);                                      \
        mma16816(acc + 4,  af, &wf0[2]);                                      \
        mma16816(acc + 8,  af, &wf1[0]);                                      \
        mma16816(acc + 12, af, &wf1[2]);                                      \
    } while (0)

    for (int t = 0; t < TT; t++) {
        const uint32_t rbo = (uint32_t)(t & 1) * ASZ;
        const uint32_t wbo = (uint32_t)((t + 1) & 1) * ASZ;
        const uint32_t ph  = (uint32_t)(t & 1) ^ 1u;   // parity for this step's waits

        float acc[16];
#pragma unroll
        for (int q = 0; q < 16; q++) acc[q] = 0.0f;

        // hoist emb(t+1) LDG into registers (latency hidden under [C])
        const bool doemb = (t < TT - 1) && (tid < 64);
        uint4 ev;
        if (doemb)
            ev = __ldg((const uint4*)(d_Ef + (size_t)((t + 1) * BN + b0 + (tid >> 1)) * 16)
                       + (tid & 1));

        // [A] part1: locally-produced kcs (own column region + ext) ----------
        {
            const int cbk = cb * 4;
#pragma unroll
            for (int i = 0; i < 4; i++) DO_KC(cbk + i);
            DO_KC(16);
        }

        // [C] peer kcs with fine-grained per-source waits ---------------------
#pragma unroll
        for (int rr = 1; rr < 4; rr++) {
            const int r = (cb + rr) & 3;
            if (t > 0) mbar_wait_cl(sb + SO_MB + r * 8, ph);
            if (rr == 1) {
                uint32_t af[4];
                ldsm_x4(af, (aBase + rbo + kbp) ^ aXor);
                mma16816(acc,      af, &wfp0[0]);
                mma16816(acc + 4,  af, &wfp0[2]);
                mma16816(acc + 8,  af, &wfp1[0]);
                mma16816(acc + 12, af, &wfp1[2]);
#pragma unroll
                for (int i = 1; i < 4; i++) DO_KC((r << 2) + i);
            } else {
#pragma unroll
                for (int i = 0; i < 4; i++) DO_KC((r << 2) + i);
            }
        }

        // [D] store the prefetched emb(t+1) ext into A[wb] -------------------
        if (doemb) {
            int row = tid >> 1, g2 = tid & 1;
            int off = row * RS + (32 + g2) * 16;
            int sw  = off ^ ((row & 7) << 4);
            *(uint4*)(base + SO_A + wbo + sw) = ev;
        }

        // [D] gates: each thread owns all 4 gates of its units (R12 path) ----
        __half* Hb = (__half*)(base + SO_HB);
#pragma unroll
        for (int slot = 0; slot < 2; slot++) {
#pragma unroll
            for (int rh = 0; rh < 2; rh++) {
                int ai = slot * 4 + rh * 2;
                float zg = acc[ai],     zi = acc[ai + 1];
                float zf = acc[8 + ai], zo = acc[8 + ai + 1];
                int q = slot * 2 + rh;
                float c = ftanha(zg) * fsigt(zi) + cst[q] * fsigt(zf);
                cst[q] = c;
                float h = ftanha(c) * fsigt(zo);
                int row = mh * 16 + (l >> 2) + rh * 8;        // 0..31
                int u   = nq * 8 + slot * 4 + (l & 3);        // 0..63
                if (t < TT - 1) {
                    Hb[row * 64 + u] = __float2half(h);
                } else {
                    d_Hf[(size_t)(b0 + row) * HID + ug0 + u] = h;
                }
            }
        }
        if (t == TT - 1) break;

        // [E] broadcast my h slice -> all 4 ranks' A[wb] (peers first) -------
        __syncthreads();
        if (tid < 256) {
            int row = tid >> 3, chunk = tid & 7;          // 256 granules of 16B
            uint4 v = *(const uint4*)(base + SO_HB + row * 128 + chunk * 16);
            int off = row * RS + cb * 128 + chunk * 16;
            uint32_t dst = (uint32_t)(SO_A) + wbo + (uint32_t)(off ^ ((row & 7) << 4));
#pragma unroll
            for (int rr = 1; rr <= GRPSZ; rr++)
                st_cluster_u4(peer[(cb + rr) & 3] + dst, v);
        }

        // [F] order stores; signal each peer's mbar slot for my rank ---------
        __syncthreads();
        if (tid < 3) {
            const int r = (cb + 1 + tid) & 3;
            mbar_arrive_remote(peer[r] + SO_MB + cb * 8);
        }
    }
    CLUSTER_SYNC();   // no CTA exits while peers may still write its SMEM
#undef DO_KC
}

// ---------------- final projection -----------------------------------------
__global__ void proj_kernel(const float* __restrict__ Wph, const float* __restrict__ bpv,
                            float* __restrict__ out) {
    __shared__ float Ws[HID * CLS];
    int tid = threadIdx.x;
    for (int idx = tid; idx < HID * CLS; idx += blockDim.x) Ws[idx] = Wph[idx];
    __syncthreads();
    int b = blockIdx.x * blockDim.x + tid;
    float acc[CLS];
#pragma unroll
    for (int c = 0; c < CLS; c++) acc[c] = bpv[c];
    const float* hrow = d_Hf + (size_t)b * HID;
    for (int k = 0; k < HID; k++) {
        float h = hrow[k];
#pragma unroll
        for (int c = 0; c < CLS; c++) acc[c] += h * Ws[k * CLS + c];
    }
#pragma unroll
    for (int c = 0; c < CLS; c++) out[b * CLS + c] = acc[c];
}

extern "C" void kernel_launch(void* const* d_in, const int* in_sizes, int n_in,
                              void* d_out, int out_size) {
    const int*   x   = (const int*)d_in[0];
    const float* emb = (const float*)d_in[1];
    const float* Wgx = (const float*)d_in[2];
    const float* Wgh = (const float*)d_in[3];
    const float* bg  = (const float*)d_in[4];
    const float* Wix = (const float*)d_in[5];
    const float* Wih = (const float*)d_in[6];
    const float* bi  = (const float*)d_in[7];
    const float* Wfx = (const float*)d_in[8];
    const float* Wfh = (const float*)d_in[9];
    const float* bf  = (const float*)d_in[10];
    const float* Wox = (const float*)d_in[11];
    const float* Woh = (const float*)d_in[12];
    const float* bo  = (const float*)d_in[13];
    const float* Wph = (const float*)d_in[14];
    const float* bp  = (const float*)d_in[15];
    float* out = (float*)d_out;

    embed_kernel<<<(BN * TT) / 256, 256>>>(x, emb);

    cudaFuncSetAttribute(lstm_kernel, cudaFuncAttributeMaxDynamicSharedMemorySize, SMEM_REQ);
    lstm_kernel<<<NCTA, NTHR, SMEM_REQ>>>(Wgh, Wih, Wfh, Woh,
                                          Wgx, Wix, Wfx, Wox,
                                          bg, bi, bf, bo);

    proj_kernel<<<BN / 128, 128>>>(Wph, bp, out);
}